// round 2
// baseline (speedup 1.0000x reference)
#include <cuda_runtime.h>

#define Bsz 256
#define Tn  100
#define Fn  256
#define Hn  1024
#define On  8

#define ALPHA 0.9048374180359595f   // exp(-0.001/0.01)
#define BETA  0.8187307530779818f   // exp(-0.001/0.005)

// Output layout inside d_out (flattened tuple, reference return order):
//   out [B, T+1, O], s1 [B,T,H], s2 [B,T,H], v1 [B,T,H], v2 [B,T,H]
#define OUT_OFF 0
#define S1_OFF  (Bsz*(Tn+1)*On)                 // 206848
#define S2_OFF  (S1_OFF + Bsz*Tn*Hn)            // 26421248
#define V1_OFF  (S2_OFF + Bsz*Tn*Hn)            // 52635648
#define V2_OFF  (V1_OFF + Bsz*Tn*Hn)            // 78850048

// Scratch (allocation-free: __device__ globals)
__device__ float g_H1[(size_t)Bsz * Tn * Hn];   // inputs @ W0   (100 MB)
__device__ float g_cur1[Bsz * Hn];
__device__ float g_cur2[Bsz * Hn];

// ---------------------------------------------------------------------------
// Classic fp32 SGEMM: C[M,N] = A[M,K] @ B[K,N], all row-major.
// Sequential-k FFMA chain per output element (matches Eigen gebp association).
// ---------------------------------------------------------------------------
__global__ __launch_bounds__(256) void sgemm_kernel(
    const float* __restrict__ A, const float* __restrict__ B,
    float* __restrict__ C, int M, int N, int K)
{
    __shared__ float As[8][128];
    __shared__ float Bs[8][128];

    int tid  = threadIdx.x;
    int brow = blockIdx.y * 128;
    int bcol = blockIdx.x * 128;

    int arow = tid >> 1;            // 0..127
    int acol = (tid & 1) << 2;      // 0 or 4
    int brw  = tid >> 5;            // 0..7
    int bcl  = (tid & 31) << 2;     // 0..124

    int ty = (tid >> 4) << 3;       // 0..120
    int tx = (tid & 15) << 3;       // 0..120

    float acc[8][8];
#pragma unroll
    for (int i = 0; i < 8; i++)
#pragma unroll
        for (int j = 0; j < 8; j++) acc[i][j] = 0.f;

    for (int k0 = 0; k0 < K; k0 += 8) {
        float4 a4 = *(const float4*)(A + (size_t)(brow + arow) * K + k0 + acol);
        As[acol + 0][arow] = a4.x;
        As[acol + 1][arow] = a4.y;
        As[acol + 2][arow] = a4.z;
        As[acol + 3][arow] = a4.w;
        *(float4*)&Bs[brw][bcl] =
            *(const float4*)(B + (size_t)(k0 + brw) * N + bcol + bcl);
        __syncthreads();

#pragma unroll
        for (int kk = 0; kk < 8; kk++) {
            float ar[8], br[8];
#pragma unroll
            for (int i = 0; i < 8; i++) ar[i] = As[kk][ty + i];
#pragma unroll
            for (int j = 0; j < 8; j++) br[j] = Bs[kk][tx + j];
#pragma unroll
            for (int i = 0; i < 8; i++)
#pragma unroll
                for (int j = 0; j < 8; j++)
                    acc[i][j] = __fmaf_rn(ar[i], br[j], acc[i][j]);
        }
        __syncthreads();
    }

#pragma unroll
    for (int i = 0; i < 8; i++) {
        float4 c0 = make_float4(acc[i][0], acc[i][1], acc[i][2], acc[i][3]);
        float4 c1 = make_float4(acc[i][4], acc[i][5], acc[i][6], acc[i][7]);
        *(float4*)(C + (size_t)(brow + ty + i) * N + bcol + tx)     = c0;
        *(float4*)(C + (size_t)(brow + ty + i) * N + bcol + tx + 4) = c1;
    }
}

// ---------------------------------------------------------------------------
// Deterministic compact active-index list from a binary spike row (Hn floats).
// 256 threads, 4 indices each, in index order (prefix-sum, no atomics).
// ---------------------------------------------------------------------------
__device__ __forceinline__ int build_list(const float* __restrict__ srow,
                                          int* __restrict__ list,
                                          int* __restrict__ wscan)
{
    int tid  = threadIdx.x;
    int lane = tid & 31;
    int wid  = tid >> 5;

    float4 s = ((const float4*)srow)[tid];
    int idx[4];
    int c = 0;
    int base = tid << 2;
    if (s.x != 0.f) idx[c++] = base;
    if (s.y != 0.f) idx[c++] = base + 1;
    if (s.z != 0.f) idx[c++] = base + 2;
    if (s.w != 0.f) idx[c++] = base + 3;

    int inc = c;
#pragma unroll
    for (int d = 1; d < 32; d <<= 1) {
        int n = __shfl_up_sync(0xffffffffu, inc, d);
        if (lane >= d) inc += n;
    }
    if (lane == 31) wscan[wid] = inc;
    __syncthreads();
    if (tid == 0) {
        int run = 0;
#pragma unroll
        for (int w = 0; w < 8; w++) { int v = wscan[w]; wscan[w] = run; run += v; }
        wscan[8] = run;
    }
    __syncthreads();
    int start = wscan[wid] + inc - c;
    for (int u = 0; u < c; u++) list[start + u] = idx[u];
    int total = wscan[8];
    __syncthreads();
    return total;
}

// Sum listed rows of M[.][Hn] (binary matmul as gather), index order, exact fp32.
// Equivalent to Eigen's sequential-k FMA chain (fma with 1.0 == fadd, 0 == skip).
__device__ __forceinline__ float4 gather_sum(const float* __restrict__ M,
                                             const int* __restrict__ list, int cnt)
{
    int tid = threadIdx.x;
    float4 acc = make_float4(0.f, 0.f, 0.f, 0.f);
    int k = 0;
    for (; k + 4 <= cnt; k += 4) {
        float4 r0 = ((const float4*)(M + (size_t)list[k + 0] * Hn))[tid];
        float4 r1 = ((const float4*)(M + (size_t)list[k + 1] * Hn))[tid];
        float4 r2 = ((const float4*)(M + (size_t)list[k + 2] * Hn))[tid];
        float4 r3 = ((const float4*)(M + (size_t)list[k + 3] * Hn))[tid];
        acc.x += r0.x; acc.y += r0.y; acc.z += r0.z; acc.w += r0.w;
        acc.x += r1.x; acc.y += r1.y; acc.z += r1.z; acc.w += r1.w;
        acc.x += r2.x; acc.y += r2.y; acc.z += r2.z; acc.w += r2.w;
        acc.x += r3.x; acc.y += r3.y; acc.z += r3.z; acc.w += r3.w;
    }
    for (; k < cnt; k++) {
        float4 r = ((const float4*)(M + (size_t)list[k] * Hn))[tid];
        acc.x += r.x; acc.y += r.y; acc.z += r.z; acc.w += r.w;
    }
    return acc;
}

// LIF elementwise update. XLA CPU compiles the fused elementwise ops with
// fp-contraction: ALPHA*cur + h -> fma, BETA*pot + new_cur -> fma.
__device__ __forceinline__ void lif_update(float cur, float pot, float h, float rec,
                                           float& ncur, float& npot, float& spk)
{
    float x = __fadd_rn(pot, -1.0f);
    spk = (x > 0.f) ? 1.f : 0.f;
    float active = __fadd_rn(1.0f, -spk);
    ncur = __fadd_rn(__fmaf_rn(ALPHA, cur, h), rec);
    npot = __fmul_rn(__fmaf_rn(BETA, pot, ncur), active);
}

// ---------------------------------------------------------------------------
// Layer-1 scan step: rec = s1[t-1] @ R0 (binary gather), LIF update.
// ---------------------------------------------------------------------------
__global__ __launch_bounds__(256) void lif1_step_kernel(
    const float* __restrict__ R0,
    float* __restrict__ v1, float* __restrict__ s1, int t)
{
    __shared__ int list[Hn];
    __shared__ int wscan[9];
    int b = blockIdx.x, tid = threadIdx.x;

    float4 h = ((const float4*)(g_H1 + ((size_t)b * Tn + t) * Hn))[tid];
    float4 rec = make_float4(0.f, 0.f, 0.f, 0.f);
    float4 pot = make_float4(0.f, 0.f, 0.f, 0.f);
    float4 cur = make_float4(0.f, 0.f, 0.f, 0.f);

    if (t > 0) {
        const float* sprev = s1 + ((size_t)b * Tn + (t - 1)) * Hn;
        int cnt = build_list(sprev, list, wscan);
        rec = gather_sum(R0, list, cnt);
        pot = ((const float4*)(v1 + ((size_t)b * Tn + (t - 1)) * Hn))[tid];
        cur = ((const float4*)(g_cur1 + (size_t)b * Hn))[tid];
    }

    float4 ncur, npot, spk;
    lif_update(cur.x, pot.x, h.x, rec.x, ncur.x, npot.x, spk.x);
    lif_update(cur.y, pot.y, h.y, rec.y, ncur.y, npot.y, spk.y);
    lif_update(cur.z, pot.z, h.z, rec.z, ncur.z, npot.z, spk.z);
    lif_update(cur.w, pot.w, h.w, rec.w, ncur.w, npot.w, spk.w);

    ((float4*)(g_cur1 + (size_t)b * Hn))[tid] = ncur;
    ((float4*)(v1 + ((size_t)b * Tn + t) * Hn))[tid] = npot;
    ((float4*)(s1 + ((size_t)b * Tn + t) * Hn))[tid] = spk;
}

// ---------------------------------------------------------------------------
// Layer-2 scan step with fused feed-forward: h2 = s1[t] @ W1 (binary gather),
// rec = s2[t-1] @ R1 (binary gather), LIF update.
// ---------------------------------------------------------------------------
__global__ __launch_bounds__(256) void lif2_step_kernel(
    const float* __restrict__ W1, const float* __restrict__ R1,
    const float* __restrict__ s1,
    float* __restrict__ v2, float* __restrict__ s2, int t)
{
    __shared__ int list[Hn];
    __shared__ int wscan[9];
    int b = blockIdx.x, tid = threadIdx.x;

    const float* s1row = s1 + ((size_t)b * Tn + t) * Hn;
    int cnt = build_list(s1row, list, wscan);
    float4 h = gather_sum(W1, list, cnt);
    __syncthreads();

    float4 rec = make_float4(0.f, 0.f, 0.f, 0.f);
    float4 pot = make_float4(0.f, 0.f, 0.f, 0.f);
    float4 cur = make_float4(0.f, 0.f, 0.f, 0.f);

    if (t > 0) {
        const float* sprev = s2 + ((size_t)b * Tn + (t - 1)) * Hn;
        int c2 = build_list(sprev, list, wscan);
        rec = gather_sum(R1, list, c2);
        pot = ((const float4*)(v2 + ((size_t)b * Tn + (t - 1)) * Hn))[tid];
        cur = ((const float4*)(g_cur2 + (size_t)b * Hn))[tid];
    }

    float4 ncur, npot, spk;
    lif_update(cur.x, pot.x, h.x, rec.x, ncur.x, npot.x, spk.x);
    lif_update(cur.y, pot.y, h.y, rec.y, ncur.y, npot.y, spk.y);
    lif_update(cur.z, pot.z, h.z, rec.z, ncur.z, npot.z, spk.z);
    lif_update(cur.w, pot.w, h.w, rec.w, ncur.w, npot.w, spk.w);

    ((float4*)(g_cur2 + (size_t)b * Hn))[tid] = ncur;
    ((float4*)(v2 + ((size_t)b * Tn + t) * Hn))[tid] = npot;
    ((float4*)(s2 + ((size_t)b * Tn + t) * Hn))[tid] = spk;
}

// ---------------------------------------------------------------------------
// Readout: h = s2 @ Wout per step, then leaky double integrator (FMA-contracted).
// ---------------------------------------------------------------------------
__global__ __launch_bounds__(256) void readout_kernel(
    const float* __restrict__ s2, const float* __restrict__ Wout,
    float* __restrict__ out)
{
    int b = blockIdx.x;
    int lane = threadIdx.x & 31;
    int w = threadIdx.x >> 5;   // 0..7

    float wreg[32];
#pragma unroll
    for (int k = 0; k < 32; k++) wreg[k] = Wout[(size_t)(lane + 32 * k) * On + w];

    if (threadIdx.x < On) out[(size_t)b * (Tn + 1) * On + threadIdx.x] = 0.f;

    float cur = 0.f, pot = 0.f;
    for (int t = 0; t < Tn; t++) {
        const float* srow = s2 + ((size_t)b * Tn + t) * Hn;
        float hsum = 0.f;
#pragma unroll
        for (int k = 0; k < 32; k++) hsum += srow[lane + 32 * k] * wreg[k];
#pragma unroll
        for (int off = 16; off; off >>= 1)
            hsum += __shfl_down_sync(0xffffffffu, hsum, off);
        hsum = __shfl_sync(0xffffffffu, hsum, 0);

        cur = __fmaf_rn(ALPHA, cur, hsum);
        pot = __fmaf_rn(BETA, pot, cur);
        if (lane == 0) out[(size_t)b * (Tn + 1) * On + (size_t)(t + 1) * On + w] = pot;
    }
}

extern "C" void kernel_launch(void* const* d_in, const int* in_sizes, int n_in,
                              void* d_out, int out_size)
{
    const float* inputs = (const float*)d_in[0];   // [256,100,256]
    const float* W0     = (const float*)d_in[1];   // [256,1024]
    const float* W1     = (const float*)d_in[2];   // [1024,1024]
    const float* R0     = (const float*)d_in[3];   // [1024,1024]
    const float* R1     = (const float*)d_in[4];   // [1024,1024]
    const float* Wout   = (const float*)d_in[5];   // [1024,8]

    float* out = (float*)d_out;
    float* s1 = out + S1_OFF;
    float* s2 = out + S2_OFF;
    float* v1 = out + V1_OFF;
    float* v2 = out + V2_OFF;

    // H1 = inputs @ W0 : [25600,256] @ [256,1024]
    {
        float* h1ptr = nullptr;
        cudaGetSymbolAddress((void**)&h1ptr, g_H1);
        dim3 grid(Hn / 128, (Bsz * Tn) / 128);
        sgemm_kernel<<<grid, 256>>>(inputs, W0, h1ptr, Bsz * Tn, Hn, Fn);
    }

    for (int t = 0; t < Tn; t++)
        lif1_step_kernel<<<Bsz, 256>>>(R0, v1, s1, t);

    for (int t = 0; t < Tn; t++)
        lif2_step_kernel<<<Bsz, 256>>>(W1, R1, s1, v2, s2, t);

    readout_kernel<<<Bsz, 256>>>(s2, Wout, out);
}

// round 3
// speedup vs baseline: 1.1495x; 1.1495x over previous
#include <cuda_runtime.h>

#define Bsz 256
#define Tn  100
#define Fn  256
#define Hn  1024
#define On  8

#define ALPHA 0.9048374180359595f   // exp(-0.001/0.01)
#define BETA  0.8187307530779818f   // exp(-0.001/0.005)

// Output layout inside d_out (flattened tuple, reference return order):
//   out [B, T+1, O], s1 [B,T,H], s2 [B,T,H], v1 [B,T,H], v2 [B,T,H]
#define S1_OFF  (Bsz*(Tn+1)*On)
#define S2_OFF  (S1_OFF + Bsz*Tn*Hn)
#define V1_OFF  (S2_OFF + Bsz*Tn*Hn)
#define V2_OFF  (V1_OFF + Bsz*Tn*Hn)

// Scratch (allocation-free: __device__ global)
__device__ float g_H1[(size_t)Bsz * Tn * Hn];   // inputs @ W0   (100 MB)

// ---------------------------------------------------------------------------
// fp32 SGEMM: C[M,N] = A[M,K] @ B[K,N], row-major. Sequential-k FFMA chain
// per output element (bit-matches Eigen gebp association). MUST stay fp32.
// ---------------------------------------------------------------------------
__global__ __launch_bounds__(256) void sgemm_kernel(
    const float* __restrict__ A, const float* __restrict__ B,
    float* __restrict__ C, int M, int N, int K)
{
    __shared__ float As[8][128];
    __shared__ float Bs[8][128];

    int tid  = threadIdx.x;
    int brow = blockIdx.y * 128;
    int bcol = blockIdx.x * 128;

    int arow = tid >> 1;
    int acol = (tid & 1) << 2;
    int brw  = tid >> 5;
    int bcl  = (tid & 31) << 2;

    int ty = (tid >> 4) << 3;
    int tx = (tid & 15) << 3;

    float acc[8][8];
#pragma unroll
    for (int i = 0; i < 8; i++)
#pragma unroll
        for (int j = 0; j < 8; j++) acc[i][j] = 0.f;

    for (int k0 = 0; k0 < K; k0 += 8) {
        float4 a4 = *(const float4*)(A + (size_t)(brow + arow) * K + k0 + acol);
        As[acol + 0][arow] = a4.x;
        As[acol + 1][arow] = a4.y;
        As[acol + 2][arow] = a4.z;
        As[acol + 3][arow] = a4.w;
        *(float4*)&Bs[brw][bcl] =
            *(const float4*)(B + (size_t)(k0 + brw) * N + bcol + bcl);
        __syncthreads();

#pragma unroll
        for (int kk = 0; kk < 8; kk++) {
            float ar[8], br[8];
#pragma unroll
            for (int i = 0; i < 8; i++) ar[i] = As[kk][ty + i];
#pragma unroll
            for (int j = 0; j < 8; j++) br[j] = Bs[kk][tx + j];
#pragma unroll
            for (int i = 0; i < 8; i++)
#pragma unroll
                for (int j = 0; j < 8; j++)
                    acc[i][j] = __fmaf_rn(ar[i], br[j], acc[i][j]);
        }
        __syncthreads();
    }

#pragma unroll
    for (int i = 0; i < 8; i++) {
        float4 c0 = make_float4(acc[i][0], acc[i][1], acc[i][2], acc[i][3]);
        float4 c1 = make_float4(acc[i][4], acc[i][5], acc[i][6], acc[i][7]);
        *(float4*)(C + (size_t)(brow + ty + i) * N + bcol + tx)     = c0;
        *(float4*)(C + (size_t)(brow + ty + i) * N + bcol + tx + 4) = c1;
    }
}

// ---------------------------------------------------------------------------
// Deterministic compact active-index list from per-thread spike registers.
// 256 threads, 4 indices each, index order (prefix-sum). Ends with a sync
// so `list` is ready for gather_sum. Caller must sync after the gather
// before the next build overwrites `list`.
// ---------------------------------------------------------------------------
__device__ __forceinline__ int build_list(float4 s,
                                          int* __restrict__ list,
                                          int* __restrict__ wscan)
{
    int tid  = threadIdx.x;
    int lane = tid & 31;
    int wid  = tid >> 5;

    int idx[4];
    int c = 0;
    int base = tid << 2;
    if (s.x != 0.f) idx[c++] = base;
    if (s.y != 0.f) idx[c++] = base + 1;
    if (s.z != 0.f) idx[c++] = base + 2;
    if (s.w != 0.f) idx[c++] = base + 3;

    int inc = c;
#pragma unroll
    for (int d = 1; d < 32; d <<= 1) {
        int n = __shfl_up_sync(0xffffffffu, inc, d);
        if (lane >= d) inc += n;
    }
    if (lane == 31) wscan[wid] = inc;
    __syncthreads();
    if (tid == 0) {
        int run = 0;
#pragma unroll
        for (int w = 0; w < 8; w++) { int v = wscan[w]; wscan[w] = run; run += v; }
        wscan[8] = run;
    }
    __syncthreads();
    int start = wscan[wid] + inc - c;
    for (int u = 0; u < c; u++) list[start + u] = idx[u];
    int total = wscan[8];
    __syncthreads();
    return total;
}

// Sum listed rows of M[.][Hn] (binary matmul as gather), index order, exact fp32.
__device__ __forceinline__ float4 gather_sum(const float* __restrict__ M,
                                             const int* __restrict__ list, int cnt)
{
    int tid = threadIdx.x;
    float4 acc = make_float4(0.f, 0.f, 0.f, 0.f);
    int k = 0;
    for (; k + 4 <= cnt; k += 4) {
        float4 r0 = ((const float4*)(M + (size_t)list[k + 0] * Hn))[tid];
        float4 r1 = ((const float4*)(M + (size_t)list[k + 1] * Hn))[tid];
        float4 r2 = ((const float4*)(M + (size_t)list[k + 2] * Hn))[tid];
        float4 r3 = ((const float4*)(M + (size_t)list[k + 3] * Hn))[tid];
        acc.x += r0.x; acc.y += r0.y; acc.z += r0.z; acc.w += r0.w;
        acc.x += r1.x; acc.y += r1.y; acc.z += r1.z; acc.w += r1.w;
        acc.x += r2.x; acc.y += r2.y; acc.z += r2.z; acc.w += r2.w;
        acc.x += r3.x; acc.y += r3.y; acc.z += r3.z; acc.w += r3.w;
    }
    for (; k < cnt; k++) {
        float4 r = ((const float4*)(M + (size_t)list[k] * Hn))[tid];
        acc.x += r.x; acc.y += r.y; acc.z += r.z; acc.w += r.w;
    }
    return acc;
}

// LIF update, FMA-contracted like XLA CPU codegen (bit-exact vs reference).
__device__ __forceinline__ void lif_update(float cur, float pot, float h, float rec,
                                           float& ncur, float& npot, float& spk)
{
    float x = __fadd_rn(pot, -1.0f);
    spk = (x > 0.f) ? 1.f : 0.f;
    float active = __fadd_rn(1.0f, -spk);
    ncur = __fadd_rn(__fmaf_rn(ALPHA, cur, h), rec);
    npot = __fmul_rn(__fmaf_rn(BETA, pot, ncur), active);
}

__device__ __forceinline__ void lif_update4(float4 cur, float4 pot, float4 h, float4 rec,
                                            float4& ncur, float4& npot, float4& spk)
{
    lif_update(cur.x, pot.x, h.x, rec.x, ncur.x, npot.x, spk.x);
    lif_update(cur.y, pot.y, h.y, rec.y, ncur.y, npot.y, spk.y);
    lif_update(cur.z, pot.z, h.z, rec.z, ncur.z, npot.z, spk.z);
    lif_update(cur.w, pot.w, h.w, rec.w, ncur.w, npot.w, spk.w);
}

// ---------------------------------------------------------------------------
// Persistent fused scan: one block per batch element runs ALL T=100 steps of
// layer1 + layer2 + readout, state in registers. No inter-block dependence.
// ---------------------------------------------------------------------------
__global__ __launch_bounds__(256) void snn_scan_kernel(
    const float* __restrict__ R0, const float* __restrict__ W1,
    const float* __restrict__ R1, const float* __restrict__ Wout,
    float* __restrict__ out,
    float* __restrict__ s1g, float* __restrict__ s2g,
    float* __restrict__ v1g, float* __restrict__ v2g)
{
    __shared__ float sWout[Hn * On];   // 32 KB
    __shared__ int   list[Hn];         // 4 KB
    __shared__ int   wscan[9];
    __shared__ float wsum[8][On];      // per-warp readout partials
    __shared__ float hro[On];

    int b   = blockIdx.x;
    int tid = threadIdx.x;
    int lane = tid & 31;
    int wid  = tid >> 5;

    // Preload Wout into shared once (8 float4 per thread).
#pragma unroll
    for (int i = 0; i < 8; i++)
        ((float4*)sWout)[tid + 256 * i] = ((const float4*)Wout)[tid + 256 * i];

    if (tid < On) out[(size_t)b * (Tn + 1) * On + tid] = 0.f;

    float4 z = make_float4(0.f, 0.f, 0.f, 0.f);
    float4 cur1 = z, pot1 = z, spk1 = z;
    float4 cur2 = z, pot2 = z, spk2 = z;
    float cur_ro = 0.f, pot_ro = 0.f;   // meaningful on tid < 8 only

    const float* h1base = g_H1 + (size_t)b * Tn * Hn;
    size_t rowbase = (size_t)b * Tn * Hn;

    __syncthreads();

    for (int t = 0; t < Tn; t++) {
        // ----- layer 1 -----
        float4 h1 = ((const float4*)(h1base + (size_t)t * Hn))[tid];
        float4 rec1 = z;
        if (t > 0) {
            int cnt = build_list(spk1, list, wscan);
            rec1 = gather_sum(R0, list, cnt);
            __syncthreads();
        }
        float4 ncur, npot;
        lif_update4(cur1, pot1, h1, rec1, ncur, npot, spk1);
        cur1 = ncur; pot1 = npot;
        ((float4*)(v1g + rowbase + (size_t)t * Hn))[tid] = pot1;
        ((float4*)(s1g + rowbase + (size_t)t * Hn))[tid] = spk1;

        // ----- layer 2: h2 = s1[t] @ W1 (binary gather) -----
        int cnt1 = build_list(spk1, list, wscan);
        float4 h2 = gather_sum(W1, list, cnt1);
        __syncthreads();

        float4 rec2 = z;
        if (t > 0) {
            int cnt2 = build_list(spk2, list, wscan);
            rec2 = gather_sum(R1, list, cnt2);
            __syncthreads();
        }
        lif_update4(cur2, pot2, h2, rec2, ncur, npot, spk2);
        cur2 = ncur; pot2 = npot;
        ((float4*)(v2g + rowbase + (size_t)t * Hn))[tid] = pot2;
        ((float4*)(s2g + rowbase + (size_t)t * Hn))[tid] = spk2;

        // ----- readout: h_ro = s2[t] @ Wout, then leaky double integrator -----
        float pacc[On];
#pragma unroll
        for (int o = 0; o < On; o++) pacc[o] = 0.f;
        int base = tid << 2;
        if (spk2.x != 0.f) {
#pragma unroll
            for (int o = 0; o < On; o++) pacc[o] += sWout[(base + 0) * On + o];
        }
        if (spk2.y != 0.f) {
#pragma unroll
            for (int o = 0; o < On; o++) pacc[o] += sWout[(base + 1) * On + o];
        }
        if (spk2.z != 0.f) {
#pragma unroll
            for (int o = 0; o < On; o++) pacc[o] += sWout[(base + 2) * On + o];
        }
        if (spk2.w != 0.f) {
#pragma unroll
            for (int o = 0; o < On; o++) pacc[o] += sWout[(base + 3) * On + o];
        }
#pragma unroll
        for (int o = 0; o < On; o++) {
            float v = pacc[o];
#pragma unroll
            for (int off = 16; off; off >>= 1)
                v += __shfl_down_sync(0xffffffffu, v, off);
            if (lane == 0) wsum[wid][o] = v;
        }
        __syncthreads();
        if (tid < On) {
            float tot = 0.f;
#pragma unroll
            for (int w = 0; w < 8; w++) tot += wsum[w][tid];
            cur_ro = __fmaf_rn(ALPHA, cur_ro, tot);
            pot_ro = __fmaf_rn(BETA, pot_ro, cur_ro);
            out[(size_t)b * (Tn + 1) * On + (size_t)(t + 1) * On + tid] = pot_ro;
        }
        __syncthreads();
        (void)hro;
    }
}

extern "C" void kernel_launch(void* const* d_in, const int* in_sizes, int n_in,
                              void* d_out, int out_size)
{
    const float* inputs = (const float*)d_in[0];   // [256,100,256]
    const float* W0     = (const float*)d_in[1];   // [256,1024]
    const float* W1     = (const float*)d_in[2];   // [1024,1024]
    const float* R0     = (const float*)d_in[3];   // [1024,1024]
    const float* R1     = (const float*)d_in[4];   // [1024,1024]
    const float* Wout   = (const float*)d_in[5];   // [1024,8]

    float* out = (float*)d_out;
    float* s1 = out + S1_OFF;
    float* s2 = out + S2_OFF;
    float* v1 = out + V1_OFF;
    float* v2 = out + V2_OFF;

    float* h1ptr = nullptr;
    cudaGetSymbolAddress((void**)&h1ptr, g_H1);

    // H1 = inputs @ W0 : [25600,256] @ [256,1024]
    {
        dim3 grid(Hn / 128, (Bsz * Tn) / 128);
        sgemm_kernel<<<grid, 256>>>(inputs, W0, h1ptr, Bsz * Tn, Hn, Fn);
    }

    // Fused persistent scan: layer1 + layer2 + readout, one block per batch row.
    snn_scan_kernel<<<Bsz, 256>>>(R0, W1, R1, Wout, out, s1, s2, v1, v2);
}

// round 4
// speedup vs baseline: 1.2701x; 1.1049x over previous
#include <cuda_runtime.h>

#define Bsz 256
#define Tn  100
#define Fn  256
#define Hn  1024
#define On  8
#define NT  512   // scan threads per block

#define ALPHA 0.9048374180359595f   // exp(-0.001/0.01)
#define BETA  0.8187307530779818f   // exp(-0.001/0.005)

// Output layout inside d_out (flattened tuple, reference return order):
//   out [B, T+1, O], s1 [B,T,H], s2 [B,T,H], v1 [B,T,H], v2 [B,T,H]
#define S1_OFF  (Bsz*(Tn+1)*On)
#define S2_OFF  (S1_OFF + Bsz*Tn*Hn)
#define V1_OFF  (S2_OFF + Bsz*Tn*Hn)
#define V2_OFF  (V1_OFF + Bsz*Tn*Hn)

// Scratch (allocation-free: __device__ global)
__device__ float g_H1[(size_t)Bsz * Tn * Hn];   // inputs @ W0   (100 MB)

// ---------------------------------------------------------------------------
// fp32 SGEMM: C[M,N] = A[M,K] @ B[K,N], row-major. Sequential-k FFMA chain
// per output element (bit-matches reference association). MUST stay fp32.
// ---------------------------------------------------------------------------
__global__ __launch_bounds__(256) void sgemm_kernel(
    const float* __restrict__ A, const float* __restrict__ B,
    float* __restrict__ C, int M, int N, int K)
{
    __shared__ float As[8][128];
    __shared__ float Bs[8][128];

    int tid  = threadIdx.x;
    int brow = blockIdx.y * 128;
    int bcol = blockIdx.x * 128;

    int arow = tid >> 1;
    int acol = (tid & 1) << 2;
    int brw  = tid >> 5;
    int bcl  = (tid & 31) << 2;

    int ty = (tid >> 4) << 3;
    int tx = (tid & 15) << 3;

    float acc[8][8];
#pragma unroll
    for (int i = 0; i < 8; i++)
#pragma unroll
        for (int j = 0; j < 8; j++) acc[i][j] = 0.f;

    for (int k0 = 0; k0 < K; k0 += 8) {
        float4 a4 = *(const float4*)(A + (size_t)(brow + arow) * K + k0 + acol);
        As[acol + 0][arow] = a4.x;
        As[acol + 1][arow] = a4.y;
        As[acol + 2][arow] = a4.z;
        As[acol + 3][arow] = a4.w;
        *(float4*)&Bs[brw][bcl] =
            *(const float4*)(B + (size_t)(k0 + brw) * N + bcol + bcl);
        __syncthreads();

#pragma unroll
        for (int kk = 0; kk < 8; kk++) {
            float ar[8], br[8];
#pragma unroll
            for (int i = 0; i < 8; i++) ar[i] = As[kk][ty + i];
#pragma unroll
            for (int j = 0; j < 8; j++) br[j] = Bs[kk][tx + j];
#pragma unroll
            for (int i = 0; i < 8; i++)
#pragma unroll
                for (int j = 0; j < 8; j++)
                    acc[i][j] = __fmaf_rn(ar[i], br[j], acc[i][j]);
        }
        __syncthreads();
    }

#pragma unroll
    for (int i = 0; i < 8; i++) {
        float4 c0 = make_float4(acc[i][0], acc[i][1], acc[i][2], acc[i][3]);
        float4 c1 = make_float4(acc[i][4], acc[i][5], acc[i][6], acc[i][7]);
        *(float4*)(C + (size_t)(brow + ty + i) * N + bcol + tx)     = c0;
        *(float4*)(C + (size_t)(brow + ty + i) * N + bcol + tx + 4) = c1;
    }
}

// ---------------------------------------------------------------------------
// Deterministic compact active-index list (index order) from per-thread
// float2 spike regs. NT=512 threads, <=2 candidates each, 16-warp scan.
// ---------------------------------------------------------------------------
__device__ __forceinline__ int build_list2(float2 s, int* __restrict__ list,
                                           int* __restrict__ wscan)
{
    int tid  = threadIdx.x;
    int lane = tid & 31;
    int wid  = tid >> 5;

    int idx[2];
    int c = 0;
    int base = tid << 1;
    if (s.x != 0.f) idx[c++] = base;
    if (s.y != 0.f) idx[c++] = base + 1;

    int inc = c;
#pragma unroll
    for (int d = 1; d < 32; d <<= 1) {
        int n = __shfl_up_sync(0xffffffffu, inc, d);
        if (lane >= d) inc += n;
    }
    if (lane == 31) wscan[wid] = inc;
    __syncthreads();
    if (tid == 0) {
        int run = 0;
#pragma unroll
        for (int w = 0; w < 16; w++) { int v = wscan[w]; wscan[w] = run; run += v; }
        wscan[16] = run;
    }
    __syncthreads();
    int start = wscan[wid] + inc - c;
    if (c > 0) list[start] = idx[0];
    if (c > 1) list[start + 1] = idx[1];
    int total = wscan[16];
    __syncthreads();
    return total;
}

#define ACC2(a, r) { (a).x += (r).x; (a).y += (r).y; }
#define ROW2(M, k) (((const float2*)((M) + (size_t)(k) * Hn))[tid])

// Single-list gather: sum listed rows in index order (exact fp32), unroll 8.
__device__ __forceinline__ float2 gather2(const float* __restrict__ M,
                                          const int* __restrict__ list, int cnt)
{
    int tid = threadIdx.x;
    float2 acc = make_float2(0.f, 0.f);
    int k = 0;
    for (; k + 8 <= cnt; k += 8) {
        float2 r0 = ROW2(M, list[k+0]); float2 r1 = ROW2(M, list[k+1]);
        float2 r2 = ROW2(M, list[k+2]); float2 r3 = ROW2(M, list[k+3]);
        float2 r4 = ROW2(M, list[k+4]); float2 r5 = ROW2(M, list[k+5]);
        float2 r6 = ROW2(M, list[k+6]); float2 r7 = ROW2(M, list[k+7]);
        ACC2(acc, r0); ACC2(acc, r1); ACC2(acc, r2); ACC2(acc, r3);
        ACC2(acc, r4); ACC2(acc, r5); ACC2(acc, r6); ACC2(acc, r7);
    }
    for (; k < cnt; k++) { float2 r = ROW2(M, list[k]); ACC2(acc, r); }
    return acc;
}

// Dual-list gather: two independent gather streams interleaved for 2x MLP.
// Per-list accumulation order identical to sequential gather (bit-exact).
__device__ __forceinline__ void dual_gather2(
    const float* __restrict__ M0, const int* __restrict__ l0, int c0,
    const float* __restrict__ M1, const int* __restrict__ l1, int c1,
    float2& a0, float2& a1)
{
    int tid = threadIdx.x;
    a0 = make_float2(0.f, 0.f);
    a1 = make_float2(0.f, 0.f);
    int cmin = min(c0, c1);
    int k = 0;
    for (; k + 4 <= cmin; k += 4) {
        float2 p0 = ROW2(M0, l0[k+0]); float2 p1 = ROW2(M0, l0[k+1]);
        float2 p2 = ROW2(M0, l0[k+2]); float2 p3 = ROW2(M0, l0[k+3]);
        float2 q0 = ROW2(M1, l1[k+0]); float2 q1 = ROW2(M1, l1[k+1]);
        float2 q2 = ROW2(M1, l1[k+2]); float2 q3 = ROW2(M1, l1[k+3]);
        ACC2(a0, p0); ACC2(a0, p1); ACC2(a0, p2); ACC2(a0, p3);
        ACC2(a1, q0); ACC2(a1, q1); ACC2(a1, q2); ACC2(a1, q3);
    }
    int k0 = k;
    for (; k0 + 8 <= c0; k0 += 8) {
        float2 r0 = ROW2(M0, l0[k0+0]); float2 r1 = ROW2(M0, l0[k0+1]);
        float2 r2 = ROW2(M0, l0[k0+2]); float2 r3 = ROW2(M0, l0[k0+3]);
        float2 r4 = ROW2(M0, l0[k0+4]); float2 r5 = ROW2(M0, l0[k0+5]);
        float2 r6 = ROW2(M0, l0[k0+6]); float2 r7 = ROW2(M0, l0[k0+7]);
        ACC2(a0, r0); ACC2(a0, r1); ACC2(a0, r2); ACC2(a0, r3);
        ACC2(a0, r4); ACC2(a0, r5); ACC2(a0, r6); ACC2(a0, r7);
    }
    for (; k0 < c0; k0++) { float2 r = ROW2(M0, l0[k0]); ACC2(a0, r); }
    int k1 = k;
    for (; k1 + 8 <= c1; k1 += 8) {
        float2 r0 = ROW2(M1, l1[k1+0]); float2 r1 = ROW2(M1, l1[k1+1]);
        float2 r2 = ROW2(M1, l1[k1+2]); float2 r3 = ROW2(M1, l1[k1+3]);
        float2 r4 = ROW2(M1, l1[k1+4]); float2 r5 = ROW2(M1, l1[k1+5]);
        float2 r6 = ROW2(M1, l1[k1+6]); float2 r7 = ROW2(M1, l1[k1+7]);
        ACC2(a1, r0); ACC2(a1, r1); ACC2(a1, r2); ACC2(a1, r3);
        ACC2(a1, r4); ACC2(a1, r5); ACC2(a1, r6); ACC2(a1, r7);
    }
    for (; k1 < c1; k1++) { float2 r = ROW2(M1, l1[k1]); ACC2(a1, r); }
}

// LIF update, FMA-contracted like the reference codegen (bit-exact).
__device__ __forceinline__ void lif_update(float cur, float pot, float h, float rec,
                                           float& ncur, float& npot, float& spk)
{
    float x = __fadd_rn(pot, -1.0f);
    spk = (x > 0.f) ? 1.f : 0.f;
    float active = __fadd_rn(1.0f, -spk);
    ncur = __fadd_rn(__fmaf_rn(ALPHA, cur, h), rec);
    npot = __fmul_rn(__fmaf_rn(BETA, pot, ncur), active);
}

__device__ __forceinline__ void lif_update2(float2 cur, float2 pot, float2 h, float2 rec,
                                            float2& ncur, float2& npot, float2& spk)
{
    lif_update(cur.x, pot.x, h.x, rec.x, ncur.x, npot.x, spk.x);
    lif_update(cur.y, pot.y, h.y, rec.y, ncur.y, npot.y, spk.y);
}

// ---------------------------------------------------------------------------
// Persistent fused scan: one block per batch element, all T steps of
// layer1 + layer2 + readout, state in registers. 512 threads, 2 H-elems each.
// Per step: phase A = dual gather (R0 from spk1[t-1], R1 from spk2[t-1]),
// phase B = gather (W1 from spk1[t]), then readout.
// ---------------------------------------------------------------------------
__global__ __launch_bounds__(NT) void snn_scan_kernel(
    const float* __restrict__ R0, const float* __restrict__ W1,
    const float* __restrict__ R1, const float* __restrict__ Wout,
    float* __restrict__ out,
    float* __restrict__ s1g, float* __restrict__ s2g,
    float* __restrict__ v1g, float* __restrict__ v2g)
{
    __shared__ float sWout[Hn * On];   // 32 KB
    __shared__ int   listA[Hn];        // 4 KB
    __shared__ int   listB[Hn];        // 4 KB
    __shared__ int   wscan[17];
    __shared__ float wsum[16][On];

    int b    = blockIdx.x;
    int tid  = threadIdx.x;
    int lane = tid & 31;
    int wid  = tid >> 5;

    // Preload Wout into shared (8192 floats = 4 float4 per thread).
#pragma unroll
    for (int i = 0; i < 4; i++)
        ((float4*)sWout)[tid + NT * i] = ((const float4*)Wout)[tid + NT * i];

    if (tid < On) out[(size_t)b * (Tn + 1) * On + tid] = 0.f;

    float2 z = make_float2(0.f, 0.f);
    float2 cur1 = z, pot1 = z, spk1 = z;
    float2 cur2 = z, pot2 = z, spk2 = z;
    float cur_ro = 0.f, pot_ro = 0.f;   // live on tid < 8

    const float* h1base = g_H1 + (size_t)b * Tn * Hn;
    size_t rowbase = (size_t)b * Tn * Hn;

    __syncthreads();

    for (int t = 0; t < Tn; t++) {
        float2 h1 = ((const float2*)(h1base + (size_t)t * Hn))[tid];
        float2 rec1 = z, rec2 = z;

        // ---- phase A: independent recurrent gathers for both layers ----
        if (t > 0) {
            int c0 = build_list2(spk1, listA, wscan);
            int c1 = build_list2(spk2, listB, wscan);
            dual_gather2(R0, listA, c0, R1, listB, c1, rec1, rec2);
            __syncthreads();
        }

        // ---- layer 1 update ----
        float2 ncur, npot;
        lif_update2(cur1, pot1, h1, rec1, ncur, npot, spk1);
        cur1 = ncur; pot1 = npot;
        ((float2*)(v1g + rowbase + (size_t)t * Hn))[tid] = pot1;
        ((float2*)(s1g + rowbase + (size_t)t * Hn))[tid] = spk1;

        // ---- phase B: h2 = s1[t] @ W1 (binary gather) ----
        int c2 = build_list2(spk1, listA, wscan);
        float2 h2 = gather2(W1, listA, c2);
        __syncthreads();

        // ---- layer 2 update ----
        lif_update2(cur2, pot2, h2, rec2, ncur, npot, spk2);
        cur2 = ncur; pot2 = npot;
        ((float2*)(v2g + rowbase + (size_t)t * Hn))[tid] = pot2;
        ((float2*)(s2g + rowbase + (size_t)t * Hn))[tid] = spk2;

        // ---- readout: h_ro = s2[t] @ Wout, leaky double integrator ----
        float pacc[On];
#pragma unroll
        for (int o = 0; o < On; o++) pacc[o] = 0.f;
        int base = tid << 1;
        if (spk2.x != 0.f) {
#pragma unroll
            for (int o = 0; o < On; o++) pacc[o] += sWout[(base + 0) * On + o];
        }
        if (spk2.y != 0.f) {
#pragma unroll
            for (int o = 0; o < On; o++) pacc[o] += sWout[(base + 1) * On + o];
        }
#pragma unroll
        for (int o = 0; o < On; o++) {
            float v = pacc[o];
#pragma unroll
            for (int off = 16; off; off >>= 1)
                v += __shfl_down_sync(0xffffffffu, v, off);
            if (lane == 0) wsum[wid][o] = v;
        }
        __syncthreads();
        if (tid < On) {
            float tot = 0.f;
#pragma unroll
            for (int w = 0; w < 16; w++) tot += wsum[w][tid];
            cur_ro = __fmaf_rn(ALPHA, cur_ro, tot);
            pot_ro = __fmaf_rn(BETA, pot_ro, cur_ro);
            out[(size_t)b * (Tn + 1) * On + (size_t)(t + 1) * On + tid] = pot_ro;
        }
        __syncthreads();
    }
}

extern "C" void kernel_launch(void* const* d_in, const int* in_sizes, int n_in,
                              void* d_out, int out_size)
{
    const float* inputs = (const float*)d_in[0];   // [256,100,256]
    const float* W0     = (const float*)d_in[1];   // [256,1024]
    const float* W1     = (const float*)d_in[2];   // [1024,1024]
    const float* R0     = (const float*)d_in[3];   // [1024,1024]
    const float* R1     = (const float*)d_in[4];   // [1024,1024]
    const float* Wout   = (const float*)d_in[5];   // [1024,8]

    float* out = (float*)d_out;
    float* s1 = out + S1_OFF;
    float* s2 = out + S2_OFF;
    float* v1 = out + V1_OFF;
    float* v2 = out + V2_OFF;

    float* h1ptr = nullptr;
    cudaGetSymbolAddress((void**)&h1ptr, g_H1);

    // H1 = inputs @ W0 : [25600,256] @ [256,1024]
    {
        dim3 grid(Hn / 128, (Bsz * Tn) / 128);
        sgemm_kernel<<<grid, 256>>>(inputs, W0, h1ptr, Bsz * Tn, Hn, Fn);
    }

    // Fused persistent scan: one block per batch row.
    snn_scan_kernel<<<Bsz, NT>>>(R0, W1, R1, Wout, out, s1, s2, v1, v2);
}